// round 10
// baseline (speedup 1.0000x reference)
#include <cuda_runtime.h>
#include <cuda_fp16.h>
#include <math_constants.h>

#define NN 50000
#define EE 1600000

// ---------------- scratch (device globals) ----------------------------------
__device__ __align__(16) __half g_feat1h[NN * 128];
__device__ __align__(16) __half g_W1t[128 * 128];   // W1 transposed [n][k], fp16
__device__ __align__(16) float g_el1  [NN * 4];
__device__ __align__(16) float g_er1  [NN * 4];
__device__ __align__(16) __half g_feat2h[NN * 16];  // layer-2 features, fp16
__device__ float g_el2[NN];
__device__ float g_er2[NN];
__device__ int   g_deg[NN];
__device__ int   g_off[NN + 1];
__device__ int   g_csr[EE];
__device__ __align__(16) int g_rank[EE];
__device__ int   g_bsum[64];
__device__ int   g_ready;

__device__ __forceinline__ float leaky(float v) { return v > 0.0f ? v : 0.2f * v; }

// ---------------- prep: zero deg, reset scan state, convert W1 ---------------
__global__ void k_prep(const float* __restrict__ W1, int N) {
    int i = blockIdx.x * blockDim.x + threadIdx.x;
    if (i < N) g_deg[i] = 0;
    if (i < 128 * 128) {
        int n = i >> 7, k = i & 127;
        g_W1t[n * 128 + k] = __float2half_rn(W1[k * 128 + n]);
    }
    if (i == 0) g_ready = 0;
}

// ---------------- histogram: 4 edges/thread ----------------------------------
__global__ void k_hist(const int* __restrict__ dst, int E) {
    int e0 = (blockIdx.x * blockDim.x + threadIdx.x) * 4;
    if (e0 + 3 < E) {
        int4 d = *(const int4*)&dst[e0];
        int4 r;
        r.x = atomicAdd(&g_deg[d.x], 1);
        r.y = atomicAdd(&g_deg[d.y], 1);
        r.z = atomicAdd(&g_deg[d.z], 1);
        r.w = atomicAdd(&g_deg[d.w], 1);
        *(int4*)&g_rank[e0] = r;
    } else {
        for (int e = e0; e < E; e++)
            g_rank[e] = atomicAdd(&g_deg[dst[e]], 1);
    }
}

// ---------------- single-launch scan (all blocks resident) -------------------
__global__ void k_scan(int N, int NB) {
    __shared__ int sm[1024];
    __shared__ int s_carry;
    int t = threadIdx.x, b = blockIdx.x;
    int i = b * 1024 + t;
    int v = (i < N) ? g_deg[i] : 0;
    sm[t] = v;
    __syncthreads();
#pragma unroll
    for (int o = 1; o < 1024; o <<= 1) {
        int a = (t >= o) ? sm[t - o] : 0;
        __syncthreads();
        sm[t] += a;
        __syncthreads();
    }
    int incl = sm[t];
    if (t == 0) {
        g_bsum[b] = sm[1023];
        __threadfence();
        atomicAdd(&g_ready, 1);
    }
    if (t < 32) {
        while (*(volatile int*)&g_ready < NB) {}
        __threadfence();
        int a = (t < b) ? g_bsum[t] : 0;
        if (t + 32 < b) a += g_bsum[t + 32];
#pragma unroll
        for (int o = 16; o; o >>= 1) a += __shfl_xor_sync(0xFFFFFFFFu, a, o);
        if (t == 0) s_carry = a;
    }
    __syncthreads();
    if (i < N) g_off[i] = s_carry + incl - v;
    if (b == NB - 1 && t == 0) g_off[N] = s_carry + sm[1023];
}

// ---------------- scatter: 4 edges/thread, no atomics ------------------------
__global__ void k_scatter(const int* __restrict__ src, const int* __restrict__ dst, int E) {
    int e0 = (blockIdx.x * blockDim.x + threadIdx.x) * 4;
    if (e0 + 3 < E) {
        int4 d = *(const int4*)&dst[e0];
        int4 r = *(const int4*)&g_rank[e0];
        int4 s = *(const int4*)&src[e0];
        int o0 = g_off[d.x], o1 = g_off[d.y], o2 = g_off[d.z], o3 = g_off[d.w];
        g_csr[o0 + r.x] = s.x;
        g_csr[o1 + r.y] = s.y;
        g_csr[o2 + r.z] = s.z;
        g_csr[o3 + r.w] = s.w;
    } else {
        for (int e = e0; e < E; e++)
            g_csr[g_off[dst[e]] + g_rank[e]] = src[e];
    }
}

// ---------------- layer 1 GEMM (tensor cores) + fused el/er ------------------
#define AS_STRIDE 136
__global__ void k_gemm1(const float* __restrict__ x,
                        const float* __restrict__ al1, const float* __restrict__ ar1, int N) {
    extern __shared__ __align__(16) __half smem[];
    __half* As = smem;                     // [128][136]
    __half* Ws = smem + 128 * AS_STRIDE;   // [128][136]
    int t = threadIdx.x;
    int m0 = blockIdx.x * 128;

    {
        int r = t >> 1;
        int c0 = (t & 1) * 64;
        const uint4* srcp = (const uint4*)&g_W1t[r * 128 + c0];
        uint4* dstp = (uint4*)&Ws[r * AS_STRIDE + c0];
#pragma unroll
        for (int i = 0; i < 8; i++) dstp[i] = srcp[i];
    }
    {
        int r = t >> 1;
        int c0 = (t & 1) * 64;
        int m = m0 + r;
#pragma unroll
        for (int i = 0; i < 64; i += 4) {
            float4 v = (m < N) ? *(const float4*)&x[m * 128 + c0 + i]
                               : make_float4(0.f, 0.f, 0.f, 0.f);
            __half2 h01 = __floats2half2_rn(v.x, v.y);
            __half2 h23 = __floats2half2_rn(v.z, v.w);
            uint2 pk;
            pk.x = *(unsigned*)&h01;
            pk.y = *(unsigned*)&h23;
            *(uint2*)&As[r * AS_STRIDE + c0 + i] = pk;
        }
    }
    __syncthreads();

    int w = t >> 5, lane = t & 31;
    int g = lane >> 2, tg = lane & 3;
    int mrow = w * 16;

    float acc[16][4];
#pragma unroll
    for (int nt = 0; nt < 16; nt++)
#pragma unroll
        for (int i = 0; i < 4; i++) acc[nt][i] = 0.f;

#pragma unroll
    for (int k0 = 0; k0 < 128; k0 += 16) {
        unsigned ra0 = *(const unsigned*)&As[(mrow + g)     * AS_STRIDE + k0 + tg * 2];
        unsigned ra1 = *(const unsigned*)&As[(mrow + g + 8) * AS_STRIDE + k0 + tg * 2];
        unsigned ra2 = *(const unsigned*)&As[(mrow + g)     * AS_STRIDE + k0 + tg * 2 + 8];
        unsigned ra3 = *(const unsigned*)&As[(mrow + g + 8) * AS_STRIDE + k0 + tg * 2 + 8];
#pragma unroll
        for (int nt = 0; nt < 16; nt++) {
            unsigned rb0 = *(const unsigned*)&Ws[(nt * 8 + g) * AS_STRIDE + k0 + tg * 2];
            unsigned rb1 = *(const unsigned*)&Ws[(nt * 8 + g) * AS_STRIDE + k0 + tg * 2 + 8];
            asm volatile(
                "mma.sync.aligned.m16n8k16.row.col.f32.f16.f16.f32 "
                "{%0,%1,%2,%3}, {%4,%5,%6,%7}, {%8,%9}, {%0,%1,%2,%3};"
                : "+f"(acc[nt][0]), "+f"(acc[nt][1]), "+f"(acc[nt][2]), "+f"(acc[nt][3])
                : "r"(ra0), "r"(ra1), "r"(ra2), "r"(ra3), "r"(rb0), "r"(rb1));
        }
    }

    int m_g = m0 + mrow + g;
    int m_g8 = m_g + 8;
    if (m_g < N) {
#pragma unroll
        for (int nt = 0; nt < 16; nt++) {
            __half2 h = __floats2half2_rn(acc[nt][0], acc[nt][1]);
            *(__half2*)&g_feat1h[m_g * 128 + nt * 8 + tg * 2] = h;
        }
    }
    if (m_g8 < N) {
#pragma unroll
        for (int nt = 0; nt < 16; nt++) {
            __half2 h = __floats2half2_rn(acc[nt][2], acc[nt][3]);
            *(__half2*)&g_feat1h[m_g8 * 128 + nt * 8 + tg * 2] = h;
        }
    }

    float pl0[4] = {0, 0, 0, 0}, pr0[4] = {0, 0, 0, 0};
    float pl1[4] = {0, 0, 0, 0}, pr1[4] = {0, 0, 0, 0};
#pragma unroll
    for (int nt = 0; nt < 16; nt++) {
        float2 a = *(const float2*)&al1[nt * 8 + tg * 2];
        float2 r = *(const float2*)&ar1[nt * 8 + tg * 2];
        int h = nt >> 2;
        pl0[h] += acc[nt][0] * a.x + acc[nt][1] * a.y;
        pr0[h] += acc[nt][0] * r.x + acc[nt][1] * r.y;
        pl1[h] += acc[nt][2] * a.x + acc[nt][3] * a.y;
        pr1[h] += acc[nt][2] * r.x + acc[nt][3] * r.y;
    }
#pragma unroll
    for (int h = 0; h < 4; h++) {
#pragma unroll
        for (int o = 1; o <= 2; o <<= 1) {
            pl0[h] += __shfl_xor_sync(0xFFFFFFFFu, pl0[h], o);
            pr0[h] += __shfl_xor_sync(0xFFFFFFFFu, pr0[h], o);
            pl1[h] += __shfl_xor_sync(0xFFFFFFFFu, pl1[h], o);
            pr1[h] += __shfl_xor_sync(0xFFFFFFFFu, pr1[h], o);
        }
    }
    float el0 = (tg == 0) ? pl0[0] : (tg == 1) ? pl0[1] : (tg == 2) ? pl0[2] : pl0[3];
    float er0 = (tg == 0) ? pr0[0] : (tg == 1) ? pr0[1] : (tg == 2) ? pr0[2] : pr0[3];
    float el1v = (tg == 0) ? pl1[0] : (tg == 1) ? pl1[1] : (tg == 2) ? pl1[2] : pl1[3];
    float er1v = (tg == 0) ? pr1[0] : (tg == 1) ? pr1[1] : (tg == 2) ? pr1[2] : pr1[3];
    if (m_g < N)  { g_el1[m_g * 4 + tg] = el0;  g_er1[m_g * 4 + tg] = er0; }
    if (m_g8 < N) { g_el1[m_g8 * 4 + tg] = el1v; g_er1[m_g8 * 4 + tg] = er1v; }
}

// ---------------- layer 1 agg + finalize + fused layer-2 GEMM ----------------
__global__ void k_agg1(const float* __restrict__ b1, const float* __restrict__ W2,
                       const float* __restrict__ al2, const float* __restrict__ ar2, int N) {
    __shared__ __align__(16) float s_ex[8][128];
    __shared__ int s_s[8][32];
    int wi = threadIdx.x >> 5;
    int lane = threadIdx.x & 31;
    int n = blockIdx.x * 8 + wi;
    if (n >= N) return;
    int beg = g_off[n], end = g_off[n + 1];
    float4 er = *(const float4*)&g_er1[n * 4];

    int e2 = lane >> 4;
    int lh = lane & 15;
    int h  = lh >> 2;
    float acc[8];
#pragma unroll
    for (int i = 0; i < 8; i++) acc[i] = 0.f;
    float sm0 = 0.f, sm1 = 0.f, sm2 = 0.f, sm3 = 0.f;

    for (int base = beg; base < end; base += 32) {
        int valid = min(32, end - base);
        if (lane < valid) {
            int s = g_csr[base + lane];
            float4 el = *(const float4*)&g_el1[s * 4];
            float e0 = __expf(leaky(el.x + er.x));
            float e1 = __expf(leaky(el.y + er.y));
            float e2f = __expf(leaky(el.z + er.z));
            float e3 = __expf(leaky(el.w + er.w));
            sm0 += e0; sm1 += e1; sm2 += e2f; sm3 += e3;
            s_s[wi][lane] = s;
            *(float4*)&s_ex[wi][lane * 4] = make_float4(e0, e1, e2f, e3);
        }
        __syncwarp();
#pragma unroll 2
        for (int j0 = 0; j0 < valid; j0 += 2) {
            int j = j0 + e2;
            if (j < valid) {
                float ex = s_ex[wi][j * 4 + h];
                int sj = s_s[wi][j];
                uint4 u = *(const uint4*)&g_feat1h[sj * 128 + lh * 8];
                float2 f0 = __half22float2(*(const __half2*)&u.x);
                float2 f1 = __half22float2(*(const __half2*)&u.y);
                float2 f2 = __half22float2(*(const __half2*)&u.z);
                float2 f3 = __half22float2(*(const __half2*)&u.w);
                acc[0] = fmaf(ex, f0.x, acc[0]);
                acc[1] = fmaf(ex, f0.y, acc[1]);
                acc[2] = fmaf(ex, f1.x, acc[2]);
                acc[3] = fmaf(ex, f1.y, acc[3]);
                acc[4] = fmaf(ex, f2.x, acc[4]);
                acc[5] = fmaf(ex, f2.y, acc[5]);
                acc[6] = fmaf(ex, f3.x, acc[6]);
                acc[7] = fmaf(ex, f3.y, acc[7]);
            }
        }
        __syncwarp();
    }
#pragma unroll
    for (int i = 0; i < 8; i++) acc[i] += __shfl_xor_sync(0xFFFFFFFFu, acc[i], 16);
#pragma unroll
    for (int o = 16; o; o >>= 1) {
        sm0 += __shfl_xor_sync(0xFFFFFFFFu, sm0, o);
        sm1 += __shfl_xor_sync(0xFFFFFFFFu, sm1, o);
        sm2 += __shfl_xor_sync(0xFFFFFFFFu, sm2, o);
        sm3 += __shfl_xor_sync(0xFFFFFFFFu, sm3, o);
    }
    float ssum = (h == 0) ? sm0 : (h == 1) ? sm1 : (h == 2) ? sm2 : sm3;
    float inv = (ssum > 0.f) ? __frcp_rn(ssum) : 0.f;
    float4 ba = *(const float4*)&b1[lh * 8];
    float4 bb = *(const float4*)&b1[lh * 8 + 4];
    float v[8];
    v[0] = fmaxf(acc[0] * inv + ba.x, 0.f);
    v[1] = fmaxf(acc[1] * inv + ba.y, 0.f);
    v[2] = fmaxf(acc[2] * inv + ba.z, 0.f);
    v[3] = fmaxf(acc[3] * inv + ba.w, 0.f);
    v[4] = fmaxf(acc[4] * inv + bb.x, 0.f);
    v[5] = fmaxf(acc[5] * inv + bb.y, 0.f);
    v[6] = fmaxf(acc[6] * inv + bb.z, 0.f);
    v[7] = fmaxf(acc[7] * inv + bb.w, 0.f);
#pragma unroll
    for (int o = 4; o <= 8; o <<= 1)
#pragma unroll
        for (int i = 0; i < 8; i++) v[i] += __shfl_xor_sync(0xFFFFFFFFu, v[i], o);

    // ---- fused layer-2 GEMM + el2/er2 (x1 staged through this warp's smem) --
    float* s_x1 = &s_ex[wi][0];
    if (lane < 4) {
#pragma unroll
        for (int i = 0; i < 8; i++) s_x1[lane * 8 + i] = v[i] * 0.25f;
    }
    __syncwarp();
    int t16 = lane & 15;
    float f2 = 0.f;
#pragma unroll
    for (int k = 0; k < 32; k++)
        f2 = fmaf(s_x1[k], W2[k * 16 + t16], f2);
    if (lane < 16) g_feat2h[n * 16 + t16] = __float2half_rn(f2);
    float pl = f2 * al2[t16];
    float pr = f2 * ar2[t16];
#pragma unroll
    for (int o = 1; o <= 8; o <<= 1) {
        pl += __shfl_xor_sync(0xFFFFFFFFu, pl, o);
        pr += __shfl_xor_sync(0xFFFFFFFFu, pr, o);
    }
    if (lane == 0) { g_el2[n] = pl; g_er2[n] = pr; }
}

// ---------------- layer 2 agg (fp16 feat2, 16 edges in flight) ---------------
__global__ void k_agg2(const float* __restrict__ b2, float* __restrict__ out, int N) {
    __shared__ float s_ex[8][32];
    __shared__ int s_s[8][32];
    int wi = threadIdx.x >> 5;
    int lane = threadIdx.x & 31;
    int n = blockIdx.x * 8 + wi;
    if (n >= N) return;
    int beg = g_off[n], end = g_off[n + 1];
    float ern = g_er2[n];

    int eg = lane >> 1;        // edge group 0..15
    int hg = lane & 1;         // dim half: dims hg*8 .. hg*8+7
    float acc[8];
#pragma unroll
    for (int i = 0; i < 8; i++) acc[i] = 0.f;
    float psum = 0.f;

    for (int base = beg; base < end; base += 32) {
        int valid = min(32, end - base);
        if (lane < valid) {
            int s = g_csr[base + lane];
            float e = __expf(leaky(g_el2[s] + ern));
            psum += e;
            s_s[wi][lane] = s;
            s_ex[wi][lane] = e;
        }
        __syncwarp();
#pragma unroll 2
        for (int j0 = 0; j0 < valid; j0 += 16) {
            int j = j0 + eg;
            if (j < valid) {
                float ex = s_ex[wi][j];
                int sj = s_s[wi][j];
                uint4 u = *(const uint4*)&g_feat2h[sj * 16 + hg * 8];
                float2 f0 = __half22float2(*(const __half2*)&u.x);
                float2 f1 = __half22float2(*(const __half2*)&u.y);
                float2 f2 = __half22float2(*(const __half2*)&u.z);
                float2 f3 = __half22float2(*(const __half2*)&u.w);
                acc[0] = fmaf(ex, f0.x, acc[0]);
                acc[1] = fmaf(ex, f0.y, acc[1]);
                acc[2] = fmaf(ex, f1.x, acc[2]);
                acc[3] = fmaf(ex, f1.y, acc[3]);
                acc[4] = fmaf(ex, f2.x, acc[4]);
                acc[5] = fmaf(ex, f2.y, acc[5]);
                acc[6] = fmaf(ex, f3.x, acc[6]);
                acc[7] = fmaf(ex, f3.y, acc[7]);
            }
        }
        __syncwarp();
    }
    // reduce across the 16 edge groups: xor 2,4,8,16 (keeps hg partition)
#pragma unroll
    for (int o = 2; o <= 16; o <<= 1)
#pragma unroll
        for (int i = 0; i < 8; i++) acc[i] += __shfl_xor_sync(0xFFFFFFFFu, acc[i], o);
#pragma unroll
    for (int o = 16; o; o >>= 1)
        psum += __shfl_xor_sync(0xFFFFFFFFu, psum, o);
    float inv = (psum > 0.f) ? __frcp_rn(psum) : 0.f;

    // lanes 0 (dims 0-7) and 1 (dims 8-15) now hold the full sums
    float4 b2a = *(const float4*)&b2[hg * 8];
    float4 b2b = *(const float4*)&b2[hg * 8 + 4];
    float val[8];
    val[0] = acc[0] * inv + b2a.x;
    val[1] = acc[1] * inv + b2a.y;
    val[2] = acc[2] * inv + b2a.z;
    val[3] = acc[3] * inv + b2a.w;
    val[4] = acc[4] * inv + b2b.x;
    val[5] = acc[5] * inv + b2b.y;
    val[6] = acc[6] * inv + b2b.z;
    val[7] = acc[7] * inv + b2b.w;

    // log_softmax over 16 dims: per-lane max/sum over 8, combine with xor 1
    float mm = val[0];
#pragma unroll
    for (int i = 1; i < 8; i++) mm = fmaxf(mm, val[i]);
    mm = fmaxf(mm, __shfl_xor_sync(0xFFFFFFFFu, mm, 1));
    float es = 0.f;
#pragma unroll
    for (int i = 0; i < 8; i++) es += __expf(val[i] - mm);
    es += __shfl_xor_sync(0xFFFFFFFFu, es, 1);
    float lse = mm + logf(es);
    if (lane < 2) {
        *(float4*)&out[n * 16 + hg * 8] =
            make_float4(val[0] - lse, val[1] - lse, val[2] - lse, val[3] - lse);
        *(float4*)&out[n * 16 + hg * 8 + 4] =
            make_float4(val[4] - lse, val[5] - lse, val[6] - lse, val[7] - lse);
    }
}

// ---------------- launcher ---------------------------------------------------
extern "C" void kernel_launch(void* const* d_in, const int* in_sizes, int n_in,
                              void* d_out, int out_size) {
    const float* features = (const float*)d_in[0];
    const int*   src      = (const int*)  d_in[1];
    const int*   dst      = (const int*)  d_in[2];
    const float* W1       = (const float*)d_in[3];
    const float* al1      = (const float*)d_in[4];
    const float* ar1      = (const float*)d_in[5];
    const float* b1       = (const float*)d_in[6];
    const float* W2       = (const float*)d_in[7];
    const float* al2      = (const float*)d_in[8];
    const float* ar2      = (const float*)d_in[9];
    const float* b2       = (const float*)d_in[10];
    float* out = (float*)d_out;

    int N = in_sizes[0] / 128;
    int E = in_sizes[1];
    int NB = (N + 1023) / 1024;
    int E4 = (E + 3) / 4;
    int gemm_smem = 2 * 128 * AS_STRIDE * (int)sizeof(__half);

    static int configured = 0;
    if (!configured) {
        cudaFuncSetAttribute(k_gemm1, cudaFuncAttributeMaxDynamicSharedMemorySize, gemm_smem);
        configured = 1;
    }

    k_prep<<<(N + 255) / 256, 256>>>(W1, N);
    k_hist<<<(E4 + 255) / 256, 256>>>(dst, E);
    k_scan<<<NB, 1024>>>(N, NB);
    k_scatter<<<(E4 + 255) / 256, 256>>>(src, dst, E);
    k_gemm1<<<(N + 127) / 128, 256, gemm_smem>>>(features, al1, ar1, N);
    k_agg1<<<(N + 7) / 8, 256>>>(b1, W2, al2, ar2, N);
    k_agg2<<<(N + 7) / 8, 256>>>(b2, out, N);
}

// round 11
// speedup vs baseline: 1.5880x; 1.5880x over previous
#include <cuda_runtime.h>
#include <cuda_fp16.h>
#include <math_constants.h>

#define NN 50000
#define EE 1600000

// ---------------- scratch (device globals) ----------------------------------
__device__ __align__(16) __half g_feat1h[NN * 128];
__device__ __align__(16) __half g_W1t[128 * 128];   // W1 transposed [n][k], fp16
__device__ __align__(16) float g_el1  [NN * 4];
__device__ __align__(16) float g_er1  [NN * 4];
__device__ __align__(16) float g_feat2[NN * 16];
__device__ float g_el2[NN];
__device__ float g_er2[NN];
__device__ int   g_deg[NN];
__device__ int   g_off[NN + 1];
__device__ int   g_csr[EE];
__device__ __align__(16) int g_rank[EE];
__device__ int   g_bsum[64];
__device__ int   g_ready;

__device__ __forceinline__ float leaky(float v) { return v > 0.0f ? v : 0.2f * v; }

// ---------------- prep: zero deg, reset scan state, convert W1 ---------------
__global__ void k_prep(const float* __restrict__ W1, int N) {
    int i = blockIdx.x * blockDim.x + threadIdx.x;
    if (i < N) g_deg[i] = 0;
    if (i < 128 * 128) {
        int n = i >> 7, k = i & 127;
        g_W1t[n * 128 + k] = __float2half_rn(W1[k * 128 + n]);
    }
    if (i == 0) g_ready = 0;
}

// ---------------- histogram: 4 edges/thread ----------------------------------
__global__ void k_hist(const int* __restrict__ dst, int E) {
    int e0 = (blockIdx.x * blockDim.x + threadIdx.x) * 4;
    if (e0 + 3 < E) {
        int4 d = *(const int4*)&dst[e0];
        int4 r;
        r.x = atomicAdd(&g_deg[d.x], 1);
        r.y = atomicAdd(&g_deg[d.y], 1);
        r.z = atomicAdd(&g_deg[d.z], 1);
        r.w = atomicAdd(&g_deg[d.w], 1);
        *(int4*)&g_rank[e0] = r;
    } else {
        for (int e = e0; e < E; e++)
            g_rank[e] = atomicAdd(&g_deg[dst[e]], 1);
    }
}

// ---------------- single-launch scan (all blocks resident) -------------------
__global__ void k_scan(int N, int NB) {
    __shared__ int sm[1024];
    __shared__ int s_carry;
    int t = threadIdx.x, b = blockIdx.x;
    int i = b * 1024 + t;
    int v = (i < N) ? g_deg[i] : 0;
    sm[t] = v;
    __syncthreads();
#pragma unroll
    for (int o = 1; o < 1024; o <<= 1) {
        int a = (t >= o) ? sm[t - o] : 0;
        __syncthreads();
        sm[t] += a;
        __syncthreads();
    }
    int incl = sm[t];
    if (t == 0) {
        g_bsum[b] = sm[1023];
        __threadfence();
        atomicAdd(&g_ready, 1);
    }
    if (t < 32) {
        while (*(volatile int*)&g_ready < NB) {}
        __threadfence();
        int a = (t < b) ? g_bsum[t] : 0;
        if (t + 32 < b) a += g_bsum[t + 32];
#pragma unroll
        for (int o = 16; o; o >>= 1) a += __shfl_xor_sync(0xFFFFFFFFu, a, o);
        if (t == 0) s_carry = a;
    }
    __syncthreads();
    if (i < N) g_off[i] = s_carry + incl - v;
    if (b == NB - 1 && t == 0) g_off[N] = s_carry + sm[1023];
}

// ---------------- scatter: 4 edges/thread, no atomics ------------------------
__global__ void k_scatter(const int* __restrict__ src, const int* __restrict__ dst, int E) {
    int e0 = (blockIdx.x * blockDim.x + threadIdx.x) * 4;
    if (e0 + 3 < E) {
        int4 d = *(const int4*)&dst[e0];
        int4 r = *(const int4*)&g_rank[e0];
        int4 s = *(const int4*)&src[e0];
        int o0 = g_off[d.x], o1 = g_off[d.y], o2 = g_off[d.z], o3 = g_off[d.w];
        g_csr[o0 + r.x] = s.x;
        g_csr[o1 + r.y] = s.y;
        g_csr[o2 + r.z] = s.z;
        g_csr[o3 + r.w] = s.w;
    } else {
        for (int e = e0; e < E; e++)
            g_csr[g_off[dst[e]] + g_rank[e]] = src[e];
    }
}

// ---------------- layer 1 GEMM (tensor cores) + fused el/er ------------------
#define AS_STRIDE 136
__global__ void k_gemm1(const float* __restrict__ x,
                        const float* __restrict__ al1, const float* __restrict__ ar1, int N) {
    extern __shared__ __align__(16) __half smem[];
    __half* As = smem;                     // [128][136]
    __half* Ws = smem + 128 * AS_STRIDE;   // [128][136]
    int t = threadIdx.x;
    int m0 = blockIdx.x * 128;

    {
        int r = t >> 1;
        int c0 = (t & 1) * 64;
        const uint4* srcp = (const uint4*)&g_W1t[r * 128 + c0];
        uint4* dstp = (uint4*)&Ws[r * AS_STRIDE + c0];
#pragma unroll
        for (int i = 0; i < 8; i++) dstp[i] = srcp[i];
    }
    {
        int r = t >> 1;
        int c0 = (t & 1) * 64;
        int m = m0 + r;
#pragma unroll
        for (int i = 0; i < 64; i += 4) {
            float4 v = (m < N) ? *(const float4*)&x[m * 128 + c0 + i]
                               : make_float4(0.f, 0.f, 0.f, 0.f);
            __half2 h01 = __floats2half2_rn(v.x, v.y);
            __half2 h23 = __floats2half2_rn(v.z, v.w);
            uint2 pk;
            pk.x = *(unsigned*)&h01;
            pk.y = *(unsigned*)&h23;
            *(uint2*)&As[r * AS_STRIDE + c0 + i] = pk;
        }
    }
    __syncthreads();

    int w = t >> 5, lane = t & 31;
    int g = lane >> 2, tg = lane & 3;
    int mrow = w * 16;

    float acc[16][4];
#pragma unroll
    for (int nt = 0; nt < 16; nt++)
#pragma unroll
        for (int i = 0; i < 4; i++) acc[nt][i] = 0.f;

#pragma unroll
    for (int k0 = 0; k0 < 128; k0 += 16) {
        unsigned ra0 = *(const unsigned*)&As[(mrow + g)     * AS_STRIDE + k0 + tg * 2];
        unsigned ra1 = *(const unsigned*)&As[(mrow + g + 8) * AS_STRIDE + k0 + tg * 2];
        unsigned ra2 = *(const unsigned*)&As[(mrow + g)     * AS_STRIDE + k0 + tg * 2 + 8];
        unsigned ra3 = *(const unsigned*)&As[(mrow + g + 8) * AS_STRIDE + k0 + tg * 2 + 8];
#pragma unroll
        for (int nt = 0; nt < 16; nt++) {
            unsigned rb0 = *(const unsigned*)&Ws[(nt * 8 + g) * AS_STRIDE + k0 + tg * 2];
            unsigned rb1 = *(const unsigned*)&Ws[(nt * 8 + g) * AS_STRIDE + k0 + tg * 2 + 8];
            asm volatile(
                "mma.sync.aligned.m16n8k16.row.col.f32.f16.f16.f32 "
                "{%0,%1,%2,%3}, {%4,%5,%6,%7}, {%8,%9}, {%0,%1,%2,%3};"
                : "+f"(acc[nt][0]), "+f"(acc[nt][1]), "+f"(acc[nt][2]), "+f"(acc[nt][3])
                : "r"(ra0), "r"(ra1), "r"(ra2), "r"(ra3), "r"(rb0), "r"(rb1));
        }
    }

    int m_g = m0 + mrow + g;
    int m_g8 = m_g + 8;
    if (m_g < N) {
#pragma unroll
        for (int nt = 0; nt < 16; nt++) {
            __half2 h = __floats2half2_rn(acc[nt][0], acc[nt][1]);
            *(__half2*)&g_feat1h[m_g * 128 + nt * 8 + tg * 2] = h;
        }
    }
    if (m_g8 < N) {
#pragma unroll
        for (int nt = 0; nt < 16; nt++) {
            __half2 h = __floats2half2_rn(acc[nt][2], acc[nt][3]);
            *(__half2*)&g_feat1h[m_g8 * 128 + nt * 8 + tg * 2] = h;
        }
    }

    float pl0[4] = {0, 0, 0, 0}, pr0[4] = {0, 0, 0, 0};
    float pl1[4] = {0, 0, 0, 0}, pr1[4] = {0, 0, 0, 0};
#pragma unroll
    for (int nt = 0; nt < 16; nt++) {
        float2 a = *(const float2*)&al1[nt * 8 + tg * 2];
        float2 r = *(const float2*)&ar1[nt * 8 + tg * 2];
        int h = nt >> 2;
        pl0[h] += acc[nt][0] * a.x + acc[nt][1] * a.y;
        pr0[h] += acc[nt][0] * r.x + acc[nt][1] * r.y;
        pl1[h] += acc[nt][2] * a.x + acc[nt][3] * a.y;
        pr1[h] += acc[nt][2] * r.x + acc[nt][3] * r.y;
    }
#pragma unroll
    for (int h = 0; h < 4; h++) {
#pragma unroll
        for (int o = 1; o <= 2; o <<= 1) {
            pl0[h] += __shfl_xor_sync(0xFFFFFFFFu, pl0[h], o);
            pr0[h] += __shfl_xor_sync(0xFFFFFFFFu, pr0[h], o);
            pl1[h] += __shfl_xor_sync(0xFFFFFFFFu, pl1[h], o);
            pr1[h] += __shfl_xor_sync(0xFFFFFFFFu, pr1[h], o);
        }
    }
    float el0 = (tg == 0) ? pl0[0] : (tg == 1) ? pl0[1] : (tg == 2) ? pl0[2] : pl0[3];
    float er0 = (tg == 0) ? pr0[0] : (tg == 1) ? pr0[1] : (tg == 2) ? pr0[2] : pr0[3];
    float el1v = (tg == 0) ? pl1[0] : (tg == 1) ? pl1[1] : (tg == 2) ? pl1[2] : pl1[3];
    float er1v = (tg == 0) ? pr1[0] : (tg == 1) ? pr1[1] : (tg == 2) ? pr1[2] : pr1[3];
    if (m_g < N)  { g_el1[m_g * 4 + tg] = el0;  g_er1[m_g * 4 + tg] = er0; }
    if (m_g8 < N) { g_el1[m_g8 * 4 + tg] = el1v; g_er1[m_g8 * 4 + tg] = er1v; }
}

// ---------------- layer 1 agg + finalize + fused layer-2 GEMM ----------------
__global__ void k_agg1(const float* __restrict__ b1, const float* __restrict__ W2,
                       const float* __restrict__ al2, const float* __restrict__ ar2, int N) {
    __shared__ __align__(16) float s_ex[8][128];
    __shared__ int s_s[8][32];
    int wi = threadIdx.x >> 5;
    int lane = threadIdx.x & 31;
    int n = blockIdx.x * 8 + wi;
    if (n >= N) return;
    int beg = g_off[n], end = g_off[n + 1];
    float4 er = *(const float4*)&g_er1[n * 4];

    int e2 = lane >> 4;
    int lh = lane & 15;
    int h  = lh >> 2;
    float acc[8];
#pragma unroll
    for (int i = 0; i < 8; i++) acc[i] = 0.f;
    float sm0 = 0.f, sm1 = 0.f, sm2 = 0.f, sm3 = 0.f;

    for (int base = beg; base < end; base += 32) {
        int valid = min(32, end - base);
        if (lane < valid) {
            int s = g_csr[base + lane];
            float4 el = *(const float4*)&g_el1[s * 4];
            float e0 = __expf(leaky(el.x + er.x));
            float e1 = __expf(leaky(el.y + er.y));
            float e2f = __expf(leaky(el.z + er.z));
            float e3 = __expf(leaky(el.w + er.w));
            sm0 += e0; sm1 += e1; sm2 += e2f; sm3 += e3;
            s_s[wi][lane] = s;
            *(float4*)&s_ex[wi][lane * 4] = make_float4(e0, e1, e2f, e3);
        }
        __syncwarp();
#pragma unroll 2
        for (int j0 = 0; j0 < valid; j0 += 2) {
            int j = j0 + e2;
            if (j < valid) {
                float ex = s_ex[wi][j * 4 + h];
                int sj = s_s[wi][j];
                uint4 u = *(const uint4*)&g_feat1h[sj * 128 + lh * 8];
                float2 f0 = __half22float2(*(const __half2*)&u.x);
                float2 f1 = __half22float2(*(const __half2*)&u.y);
                float2 f2 = __half22float2(*(const __half2*)&u.z);
                float2 f3 = __half22float2(*(const __half2*)&u.w);
                acc[0] = fmaf(ex, f0.x, acc[0]);
                acc[1] = fmaf(ex, f0.y, acc[1]);
                acc[2] = fmaf(ex, f1.x, acc[2]);
                acc[3] = fmaf(ex, f1.y, acc[3]);
                acc[4] = fmaf(ex, f2.x, acc[4]);
                acc[5] = fmaf(ex, f2.y, acc[5]);
                acc[6] = fmaf(ex, f3.x, acc[6]);
                acc[7] = fmaf(ex, f3.y, acc[7]);
            }
        }
        __syncwarp();
    }
#pragma unroll
    for (int i = 0; i < 8; i++) acc[i] += __shfl_xor_sync(0xFFFFFFFFu, acc[i], 16);
#pragma unroll
    for (int o = 16; o; o >>= 1) {
        sm0 += __shfl_xor_sync(0xFFFFFFFFu, sm0, o);
        sm1 += __shfl_xor_sync(0xFFFFFFFFu, sm1, o);
        sm2 += __shfl_xor_sync(0xFFFFFFFFu, sm2, o);
        sm3 += __shfl_xor_sync(0xFFFFFFFFu, sm3, o);
    }
    float ssum = (h == 0) ? sm0 : (h == 1) ? sm1 : (h == 2) ? sm2 : sm3;
    float inv = (ssum > 0.f) ? __frcp_rn(ssum) : 0.f;
    float4 ba = *(const float4*)&b1[lh * 8];
    float4 bb = *(const float4*)&b1[lh * 8 + 4];
    float v[8];
    v[0] = fmaxf(acc[0] * inv + ba.x, 0.f);
    v[1] = fmaxf(acc[1] * inv + ba.y, 0.f);
    v[2] = fmaxf(acc[2] * inv + ba.z, 0.f);
    v[3] = fmaxf(acc[3] * inv + ba.w, 0.f);
    v[4] = fmaxf(acc[4] * inv + bb.x, 0.f);
    v[5] = fmaxf(acc[5] * inv + bb.y, 0.f);
    v[6] = fmaxf(acc[6] * inv + bb.z, 0.f);
    v[7] = fmaxf(acc[7] * inv + bb.w, 0.f);
#pragma unroll
    for (int o = 4; o <= 8; o <<= 1)
#pragma unroll
        for (int i = 0; i < 8; i++) v[i] += __shfl_xor_sync(0xFFFFFFFFu, v[i], o);

    float* s_x1 = &s_ex[wi][0];
    if (lane < 4) {
#pragma unroll
        for (int i = 0; i < 8; i++) s_x1[lane * 8 + i] = v[i] * 0.25f;
    }
    __syncwarp();
    int t16 = lane & 15;
    float f2 = 0.f;
#pragma unroll
    for (int k = 0; k < 32; k++)
        f2 = fmaf(s_x1[k], W2[k * 16 + t16], f2);
    if (lane < 16) g_feat2[n * 16 + t16] = f2;
    float pl = f2 * al2[t16];
    float pr = f2 * ar2[t16];
#pragma unroll
    for (int o = 1; o <= 8; o <<= 1) {
        pl += __shfl_xor_sync(0xFFFFFFFFu, pl, o);
        pr += __shfl_xor_sync(0xFFFFFFFFu, pr, o);
    }
    if (lane == 0) { g_el2[n] = pl; g_er2[n] = pr; }
}

// ---------------- layer 2 agg + log_softmax ----------------------------------
__global__ void k_agg2(const float* __restrict__ b2, float* __restrict__ out, int N) {
    __shared__ float s_ex[8][32];
    __shared__ int s_s[8][32];
    int wi = threadIdx.x >> 5;
    int lane = threadIdx.x & 31;
    int n = blockIdx.x * 8 + wi;
    if (n >= N) return;
    int beg = g_off[n], end = g_off[n + 1];
    float ern = g_er2[n];

    int eg = lane >> 2;
    int dg = lane & 3;
    float4 acc = make_float4(0.f, 0.f, 0.f, 0.f);
    float psum = 0.f;
    for (int base = beg; base < end; base += 32) {
        int valid = min(32, end - base);
        if (lane < valid) {
            int s = g_csr[base + lane];
            float e = __expf(leaky(g_el2[s] + ern));
            psum += e;
            s_s[wi][lane] = s;
            s_ex[wi][lane] = e;
        }
        __syncwarp();
        for (int j0 = 0; j0 < valid; j0 += 8) {
            int j = j0 + eg;
            if (j < valid) {
                float ex = s_ex[wi][j];
                float4 f = *(const float4*)&g_feat2[s_s[wi][j] * 16 + dg * 4];
                acc.x = fmaf(ex, f.x, acc.x);
                acc.y = fmaf(ex, f.y, acc.y);
                acc.z = fmaf(ex, f.z, acc.z);
                acc.w = fmaf(ex, f.w, acc.w);
            }
        }
        __syncwarp();
    }
#pragma unroll
    for (int o = 4; o <= 16; o <<= 1) {
        acc.x += __shfl_xor_sync(0xFFFFFFFFu, acc.x, o);
        acc.y += __shfl_xor_sync(0xFFFFFFFFu, acc.y, o);
        acc.z += __shfl_xor_sync(0xFFFFFFFFu, acc.z, o);
        acc.w += __shfl_xor_sync(0xFFFFFFFFu, acc.w, o);
    }
#pragma unroll
    for (int o = 16; o; o >>= 1)
        psum += __shfl_xor_sync(0xFFFFFFFFu, psum, o);
    float inv = (psum > 0.f) ? __frcp_rn(psum) : 0.f;
    float4 bb = *(const float4*)&b2[dg * 4];
    float4 val = make_float4(acc.x * inv + bb.x, acc.y * inv + bb.y,
                             acc.z * inv + bb.z, acc.w * inv + bb.w);

    float mm = fmaxf(fmaxf(val.x, val.y), fmaxf(val.z, val.w));
#pragma unroll
    for (int o = 1; o <= 2; o <<= 1)
        mm = fmaxf(mm, __shfl_xor_sync(0xFFFFFFFFu, mm, o));
    float es = __expf(val.x - mm) + __expf(val.y - mm) +
               __expf(val.z - mm) + __expf(val.w - mm);
#pragma unroll
    for (int o = 1; o <= 2; o <<= 1)
        es += __shfl_xor_sync(0xFFFFFFFFu, es, o);
    float lse = mm + logf(es);
    if (lane < 4) {
        *(float4*)&out[n * 16 + dg * 4] =
            make_float4(val.x - lse, val.y - lse, val.z - lse, val.w - lse);
    }
}

// ---------------- launcher: fork-join graph (gemm1 || CSR build) -------------
extern "C" void kernel_launch(void* const* d_in, const int* in_sizes, int n_in,
                              void* d_out, int out_size) {
    const float* features = (const float*)d_in[0];
    const int*   src      = (const int*)  d_in[1];
    const int*   dst      = (const int*)  d_in[2];
    const float* W1       = (const float*)d_in[3];
    const float* al1      = (const float*)d_in[4];
    const float* ar1      = (const float*)d_in[5];
    const float* b1       = (const float*)d_in[6];
    const float* W2       = (const float*)d_in[7];
    const float* al2      = (const float*)d_in[8];
    const float* ar2      = (const float*)d_in[9];
    const float* b2       = (const float*)d_in[10];
    float* out = (float*)d_out;

    int N = in_sizes[0] / 128;
    int E = in_sizes[1];
    int NB = (N + 1023) / 1024;
    int E4 = (E + 3) / 4;
    int gemm_smem = 2 * 128 * AS_STRIDE * (int)sizeof(__half);

    static cudaStream_t s2;
    static cudaEvent_t evF, evJ;
    static int configured = 0;
    if (!configured) {
        cudaFuncSetAttribute(k_gemm1, cudaFuncAttributeMaxDynamicSharedMemorySize, gemm_smem);
        cudaStreamCreateWithFlags(&s2, cudaStreamNonBlocking);
        cudaEventCreateWithFlags(&evF, cudaEventDisableTiming);
        cudaEventCreateWithFlags(&evJ, cudaEventDisableTiming);
        configured = 1;
    }

    // main stream: prep, then CSR chain; side stream: gemm1 in parallel
    k_prep<<<(N + 255) / 256, 256>>>(W1, N);
    cudaEventRecord(evF, 0);
    cudaStreamWaitEvent(s2, evF, 0);
    k_gemm1<<<(N + 127) / 128, 256, gemm_smem, s2>>>(features, al1, ar1, N);
    cudaEventRecord(evJ, s2);

    k_hist<<<(E4 + 255) / 256, 256>>>(dst, E);
    k_scan<<<NB, 1024>>>(N, NB);
    k_scatter<<<(E4 + 255) / 256, 256>>>(src, dst, E);

    cudaStreamWaitEvent(0, evJ, 0);
    k_agg1<<<(N + 7) / 8, 256>>>(b1, W2, al2, ar2, N);
    k_agg2<<<(N + 7) / 8, 256>>>(b2, out, N);
}